// round 13
// baseline (speedup 1.0000x reference)
#include <cuda_runtime.h>
#include <cuda_fp16.h>

#define NC 16       // codebooks
#define NK 16       // prototypes per codebook
#define NM 16       // output rows (M)
#define ND 64       // feature dim
#define NSPL 4      // tree depth
#define HSTR 24     // fp16 LUT row stride in halves (48B, 16B-aligned)
#define TBE 128     // encode: rows per tile
#define TBG 256     // gather: threads = rows per tile

__device__ __half             g_lut_h[NC * NK * NM];   // fp16 LUT (8KB)
__device__ unsigned long long g_codes[1 << 18];        // 262144 rows, 2MB

__device__ __forceinline__ unsigned smem_u32(const void* p) {
    unsigned a;
    asm("{ .reg .u64 t; cvta.to.shared.u64 t, %1; cvt.u32.u64 %0, t; }" : "=r"(a) : "l"(p));
    return a;
}
__device__ __forceinline__ void cpa16(unsigned dst, const void* src) {
    asm volatile("cp.async.cg.shared.global [%0], [%1], 16;\n" :: "r"(dst), "l"(src));
}
__device__ __forceinline__ void cpa_commit() { asm volatile("cp.async.commit_group;\n"); }
__device__ __forceinline__ void cpa_wait0()  { asm volatile("cp.async.wait_group 0;\n"); }

__device__ __forceinline__ void fadd2f(unsigned long long& a, float lo, float hi) {
    unsigned long long b;
    asm("mov.b64 %0, {%1, %2};" : "=l"(b) : "f"(lo), "f"(hi));
    asm("add.rn.f32x2 %0, %0, %1;" : "+l"(a) : "l"(b));
}

// ---------------------------------------------------------------------------
// Kernel A (encode + lut in one launch):
//   blocks [0, ntiles)        : encode 128 rows -> packed 64-bit code/row
//   blocks [ntiles, ntiles+16): lut[c,k,m] = sum_d B[m,d]*P[c,k,d] (fp32->fp16)
// Staging via cp.async (MLP=16/lane, no STS, no load regs), warp-autonomous.
// A layout: 16B chunk c4 of row r at slot (c4 ^ (r&15)) -> encode reads 2-way.
// ---------------------------------------------------------------------------
__global__ void __launch_bounds__(TBE, 6) encode_kernel(
    const float* __restrict__ A,
    const float* __restrict__ B,        // [M,D]
    const float* __restrict__ P,        // [C,K,D]
    const int*   __restrict__ sdim_g,   // [C,NSPL]
    const float* __restrict__ sval_g,   // [C,NSPL,8]
    int N, int ntiles)
{
    __shared__ __align__(16) float As[TBE * ND];   // 32768B (lut blocks reuse)
    __shared__ float sval16[NC * 16];
    __shared__ int   sdim[NC * NSPL];

    const int tid = threadIdx.x;

    if (blockIdx.x >= ntiles) {
        // ---- LUT block: one codebook c ----
        int c = blockIdx.x - ntiles;
        float* Bs = As;                       // [NM][ND+1] (fits in 32KB: 2080 floats)
        float* Ps = As + NM * (ND + 1);       // [NK][ND+1]
        for (int i = tid; i < NM * ND; i += TBE) Bs[(i >> 6) * (ND + 1) + (i & 63)] = B[i];
        for (int i = tid; i < NK * ND; i += TBE) Ps[(i >> 6) * (ND + 1) + (i & 63)] = P[c * NK * ND + i];
        __syncthreads();
#pragma unroll
        for (int e = 0; e < 2; e++) {
            int i = e * TBE + tid;            // 0..255
            int k = i >> 4, m = i & 15;
            float acc = 0.f;
#pragma unroll
            for (int d = 0; d < ND; d++)
                acc = fmaf(Bs[m * (ND + 1) + d], Ps[k * (ND + 1) + d], acc);
            g_lut_h[(c * NK + k) * NM + m] = __float2half_rn(acc);
        }
        return;
    }

    const long long base = (long long)blockIdx.x * TBE;
    const int w = tid >> 5, lane = tid & 31;

    // --- stage small tables first (cheap barrier: nothing slow precedes it) ---
    for (int i = tid; i < NC * 16; i += TBE) {
        int cb = i >> 4, j = i & 15;
        int src = (j == 0) ? 0 : (j == 1) ? 8 : (j == 2) ? 9 : (j == 3) ? 0
                : (j < 8) ? (12 + j) : (16 + j);
        sval16[i] = sval_g[cb * 32 + src];
    }
    if (tid < NC * NSPL) sdim[tid] = sdim_g[tid];
    __syncthreads();

    // --- warp-autonomous A staging via cp.async: warp w stages rows
    //     [w*32, w*32+32), 4 rows x 8 chunks per step, 16 cp.async/lane ---
    {
        const unsigned As_u = smem_u32(As);
        const int dr = lane >> 3, c8 = lane & 7;
        const float* gb = A + base * ND;
#pragma unroll
        for (int jr = 0; jr < 8; jr++) {
            int r = w * 32 + jr * 4 + dr;
            bool okr = (base + r < N);
#pragma unroll
            for (int jc = 0; jc < 2; jc++) {
                int c4 = jc * 8 + c8;
                if (okr)
                    cpa16(As_u + (unsigned)(r * ND + ((c4 ^ (r & 15)) << 2)) * 4,
                          gb + (long long)r * ND + c4 * 4);
            }
        }
        cpa_commit();
        cpa_wait0();
        __syncwarp();
    }

    const int r = tid;                      // warp w encodes rows it staged
    if (base + r >= N) return;
    const float* arow = As + r * ND;
    const int rx = r & 15;

    unsigned long long code = 0ull;
#pragma unroll
    for (int c = 0; c < NC; c++) {
        const int4   sd  = ((const int4*)sdim)[c];
        const float4 q0  = ((const float4*)sval16)[c * 4 + 0]; // s0, s1x, s1y, pad
        const float4 s2  = ((const float4*)sval16)[c * 4 + 1];
        const float4 s3a = ((const float4*)sval16)[c * 4 + 2];
        const float4 s3b = ((const float4*)sval16)[c * 4 + 3];

        // element d at quad (d>>2)^rx, offset d&3  (<=2-way conflicted)
        const float x0 = arow[(((sd.x >> 2) ^ rx) << 2) | (sd.x & 3)];
        const float x1 = arow[(((sd.y >> 2) ^ rx) << 2) | (sd.y & 3)];
        const float x2 = arow[(((sd.z >> 2) ^ rx) << 2) | (sd.z & 3)];
        const float x3 = arow[(((sd.w >> 2) ^ rx) << 2) | (sd.w & 3)];

        const bool  b0 = x0 > q0.x;
        const float v1 = b0 ? q0.z : q0.y;
        const bool  b1 = x1 > v1;
        const float t0 = b0 ? s2.z : s2.x;
        const float t1 = b0 ? s2.w : s2.y;
        const float v2 = b1 ? t1 : t0;
        const bool  b2 = x2 > v2;
        const float u0 = b0 ? s3b.x : s3a.x;
        const float u1 = b0 ? s3b.y : s3a.y;
        const float u2 = b0 ? s3b.z : s3a.z;
        const float u3 = b0 ? s3b.w : s3a.w;
        const float w0 = b1 ? u2 : u0;
        const float w1 = b1 ? u3 : u1;
        const float v3 = b2 ? w1 : w0;
        const bool  b3 = x3 > v3;

        const unsigned long long g =
            (unsigned long long)((((((int)b0 << 1) | (int)b1) << 1) | (int)b2) << 1 | (int)b3);
        code |= g << (4 * c);
    }
    g_codes[base + r] = code;
}

// ---------------------------------------------------------------------------
// Kernel B (gather): fp16 LUT in smem (12.3KB), 5 CTAs/SM -> 40 warps/SM.
// Per cb: 2 x LDS.128, unpack fp16->fp32, accumulate with packed f32x2 adds
// (same values & order per m lane as scalar -> bit-identical output).
// ---------------------------------------------------------------------------
__global__ void __launch_bounds__(TBG, 5) gather_kernel(
    float* __restrict__ out, int N)
{
    __shared__ __align__(16) __half lut16[NC * NK * HSTR];   // 12288B

    const int tid = threadIdx.x;
    const long long n = (long long)blockIdx.x * TBG + tid;
    const bool ok = n < N;

    // hoist the code load: no smem dependency, overlaps staging
    const unsigned long long code = ok ? g_codes[n] : 0ull;

    // stage LUT: 512 16B-chunks; thread does chunks tid and tid+256
    {
        const uint4* gl = (const uint4*)g_lut_h;
        uint4* ls = (uint4*)lut16;
#pragma unroll
        for (int s = 0; s < 2; s++) {
            int ch = s * TBG + tid;           // 0..511
            int row = ch >> 1, h = ch & 1;    // LUT row, 16B half-of-row
            ls[row * 3 + h] = gl[ch];         // HSTR=24 halves = 3 uint4
        }
    }
    __syncthreads();

    if (!ok) return;

    unsigned long long acc[8];                 // 8 packed f32x2 accumulators
#pragma unroll
    for (int j = 0; j < 8; j++) acc[j] = 0ull;

#pragma unroll
    for (int c = 0; c < NC; c++) {
        const int g = (int)((code >> (4 * c)) & 15ull);
        const uint4* lr = (const uint4*)(lut16 + (c * NK + g) * HSTR);
        uint4 a = lr[0];                       // m 0..7
        uint4 b = lr[1];                       // m 8..15
        const __half2* ah = (const __half2*)&a;
        const __half2* bh = (const __half2*)&b;
#pragma unroll
        for (int k = 0; k < 4; k++) {
            float2 fa = __half22float2(ah[k]);
            float2 fb = __half22float2(bh[k]);
            fadd2f(acc[k],     fa.x, fa.y);
            fadd2f(acc[4 + k], fb.x, fb.y);
        }
    }

    const long long Nll = N;
    const float2* accf = (const float2*)acc;
#pragma unroll
    for (int j = 0; j < 8; j++) {
        float2 p = accf[j];
        out[(long long)(2 * j)     * Nll + n] = p.x;
        out[(long long)(2 * j + 1) * Nll + n] = p.y;
    }
}

// ---------------------------------------------------------------------------
extern "C" void kernel_launch(void* const* d_in, const int* in_sizes, int n_in,
                              void* d_out, int out_size) {
    const float* A     = (const float*)d_in[0];
    const float* B     = (const float*)d_in[1];
    const float* P     = (const float*)d_in[2];
    const int*   sdims = (const int*)d_in[3];
    const float* svals = (const float*)d_in[4];
    float* out = (float*)d_out;
    int N = in_sizes[0] / ND;

    int ntiles = (N + TBE - 1) / TBE;
    encode_kernel<<<ntiles + NC, TBE>>>(A, B, P, sdims, svals, N, ntiles);
    gather_kernel<<<(N + TBG - 1) / TBG, TBG>>>(out, N);
}

// round 14
// speedup vs baseline: 1.0088x; 1.0088x over previous
#include <cuda_runtime.h>
#include <cuda_fp16.h>

#define NC 16       // codebooks
#define NK 16       // prototypes per codebook
#define NM 16       // output rows (M)
#define ND 64       // feature dim
#define NSPL 4      // tree depth
#define HSTR 24     // fp16 LUT row stride in halves (48B, 16B-aligned)
#define TB 128      // threads = rows per tile

__device__ __half g_lut_h[NC * NK * NM];   // fp16 LUT (8KB)
__device__ int    g_lut_done;              // monotonic across replays (stale LUT identical)

__device__ __forceinline__ void fadd2f(unsigned long long& a, float lo, float hi) {
    unsigned long long b;
    asm("mov.b64 %0, {%1, %2};" : "=l"(b) : "f"(lo), "f"(hi));
    asm("add.rn.f32x2 %0, %0, %1;" : "+l"(a) : "l"(b));
}

// ---------------------------------------------------------------------------
// Single fused kernel, 6 CTAs/SM (34KB smem: lut16 UNIONED into dead As).
//   blocks [0, 16)      : LUT producers (one codebook each), fp32 dot -> fp16,
//                         threadfence + atomic count. Scheduled in wave 1.
//   blocks [16, 16+nt)  : stage A (XOR-swizzled, warp-autonomous LDG+STS) ->
//                         encode (code in reg) -> poll LUT flag -> barrier ->
//                         stage fp16 LUT into the As region -> gather -> store.
// A layout: element d of row r at As[r*64 + (d ^ (r & 63))]:
//   encode reads (fixed d, lanes r): banks (d^r)&31 distinct -> conflict-free
//   staging STS: XOR permutes an already-distinct bank set -> conflict-free
// ---------------------------------------------------------------------------
__global__ void __launch_bounds__(TB, 6) fused_kernel(
    const float* __restrict__ A,
    const float* __restrict__ B,        // [M,D]
    const float* __restrict__ P,        // [C,K,D]
    const int*   __restrict__ sdim_g,   // [C,NSPL]
    const float* __restrict__ sval_g,   // [C,NSPL,8]
    float*       __restrict__ out,      // [M,N]
    int N)
{
    __shared__ __align__(16) float As[TB * ND];   // 32768B; lut blocks reuse;
    __half* lut16 = (__half*)As;                  // unioned: lut lives here AFTER encode
    __shared__ float sval16[NC * 16];             // 1024B (live through encode)
    __shared__ int   sdim[NC * NSPL];             // 256B

    const int tid = threadIdx.x;

    if (blockIdx.x < NC) {
        // ---- LUT producer: one codebook c ----
        int c = blockIdx.x;
        float* Bs = As;                       // [NM][ND+1]
        float* Ps = As + NM * (ND + 1);       // [NK][ND+1]
        for (int i = tid; i < NM * ND; i += TB) Bs[(i >> 6) * (ND + 1) + (i & 63)] = B[i];
        for (int i = tid; i < NK * ND; i += TB) Ps[(i >> 6) * (ND + 1) + (i & 63)] = P[c * NK * ND + i];
        __syncthreads();
#pragma unroll
        for (int e = 0; e < 2; e++) {
            int i = e * TB + tid;             // 0..255
            int k = i >> 4, m = i & 15;
            float acc = 0.f;
#pragma unroll
            for (int d = 0; d < ND; d++)
                acc = fmaf(Bs[m * (ND + 1) + d], Ps[k * (ND + 1) + d], acc);
            g_lut_h[(c * NK + k) * NM + m] = __float2half_rn(acc);
        }
        __syncthreads();
        if (tid == 0) { __threadfence(); atomicAdd(&g_lut_done, 1); }
        return;
    }

    // ---- tile block ----
    const long long base = (long long)(blockIdx.x - NC) * TB;
    const int w = tid >> 5, lane = tid & 31;

    // stage small tables first (cheap barrier: nothing slow precedes it)
    for (int i = tid; i < NC * 16; i += TB) {
        int cb = i >> 4, j = i & 15;
        int src = (j == 0) ? 0 : (j == 1) ? 8 : (j == 2) ? 9 : (j == 3) ? 0
                : (j < 8) ? (12 + j) : (16 + j);
        sval16[i] = sval_g[cb * 32 + src];
    }
    if (tid < NC * NSPL) sdim[tid] = sdim_g[tid];
    __syncthreads();

    // warp-autonomous A staging: warp w stages rows [w*32, w*32+32),
    // 4 rows x 8 chunks per instruction, coalesced LDG.128, XOR-swizzled STS
    {
        const int dr = lane >> 3, c8 = lane & 7;
        const float4* gb = (const float4*)(A + base * ND);
#pragma unroll
        for (int jr = 0; jr < 8; jr++) {
            int r = w * 32 + jr * 4 + dr;
            bool okr = (base + r < N);
            int rx = r & 63;
#pragma unroll
            for (int jc = 0; jc < 2; jc++) {
                int c4 = jc * 8 + c8;
                if (okr) {
                    float4 v = gb[r * 16 + c4];
                    float* p = As + r * ND;
                    int d0 = c4 << 2;
                    p[(d0 + 0) ^ rx] = v.x;
                    p[(d0 + 1) ^ rx] = v.y;
                    p[(d0 + 2) ^ rx] = v.z;
                    p[(d0 + 3) ^ rx] = v.w;
                }
            }
        }
    }
    __syncwarp();

    // ---- encode (code kept in register) ----
    const bool active = (base + tid < N);
    unsigned long long code = 0ull;
    if (active) {
        const float* arow = As + tid * ND;
        const int rx = tid & 63;
#pragma unroll
        for (int c = 0; c < NC; c++) {
            const int4   sd  = ((const int4*)sdim)[c];
            const float4 q0  = ((const float4*)sval16)[c * 4 + 0]; // s0,s1x,s1y,pad
            const float4 s2  = ((const float4*)sval16)[c * 4 + 1];
            const float4 s3a = ((const float4*)sval16)[c * 4 + 2];
            const float4 s3b = ((const float4*)sval16)[c * 4 + 3];

            const float x0 = arow[sd.x ^ rx];
            const float x1 = arow[sd.y ^ rx];
            const float x2 = arow[sd.z ^ rx];
            const float x3 = arow[sd.w ^ rx];

            const bool  b0 = x0 > q0.x;
            const float v1 = b0 ? q0.z : q0.y;
            const bool  b1 = x1 > v1;
            const float t0 = b0 ? s2.z : s2.x;
            const float t1 = b0 ? s2.w : s2.y;
            const float v2 = b1 ? t1 : t0;
            const bool  b2 = x2 > v2;
            const float u0 = b0 ? s3b.x : s3a.x;
            const float u1 = b0 ? s3b.y : s3a.y;
            const float u2 = b0 ? s3b.z : s3a.z;
            const float u3 = b0 ? s3b.w : s3a.w;
            const float w0 = b1 ? u2 : u0;
            const float w1 = b1 ? u3 : u1;
            const float v3 = b2 ? w1 : w0;
            const bool  b3 = x3 > v3;

            const unsigned long long g =
                (unsigned long long)((((((int)b0 << 1) | (int)b1) << 1) | (int)b2) << 1 | (int)b3);
            code |= g << (4 * c);
        }
    }

    // ---- wait for LUT (wave-1 producers; staging+encode hid the latency) ----
    if (tid == 0) {
        while (atomicAdd(&g_lut_done, 0) < NC) __nanosleep(100);
        __threadfence();
    }
    __syncthreads();   // all warps done reading As before overwrite

    // stage fp16 LUT into the (dead) As region: 512 16B-chunks, 4 per thread
    {
        const uint4* gl = (const uint4*)g_lut_h;
        uint4* ls = (uint4*)lut16;
#pragma unroll
        for (int s = 0; s < 4; s++) {
            int ch = s * TB + tid;            // 0..511
            int row = ch >> 1, h = ch & 1;    // LUT row, 16B half-of-row
            ls[row * 3 + h] = gl[ch];         // HSTR=24 halves = 3 uint4
        }
    }
    __syncthreads();

    if (!active) return;

    // ---- gather: per cb 2 x LDS.128, unpack fp16->fp32, packed f32x2 adds ----
    unsigned long long acc[8];
#pragma unroll
    for (int j = 0; j < 8; j++) acc[j] = 0ull;

#pragma unroll
    for (int c = 0; c < NC; c++) {
        const int g = (int)((code >> (4 * c)) & 15ull);
        const uint4* lr = (const uint4*)(lut16 + (c * NK + g) * HSTR);
        uint4 a = lr[0];                       // m 0..7
        uint4 b = lr[1];                       // m 8..15
        const __half2* ah = (const __half2*)&a;
        const __half2* bh = (const __half2*)&b;
#pragma unroll
        for (int k = 0; k < 4; k++) {
            float2 fa = __half22float2(ah[k]);
            float2 fb = __half22float2(bh[k]);
            fadd2f(acc[k],     fa.x, fa.y);
            fadd2f(acc[4 + k], fb.x, fb.y);
        }
    }

    const long long n = base + tid;
    const long long Nll = N;
    const float2* accf = (const float2*)acc;
#pragma unroll
    for (int j = 0; j < 8; j++) {
        float2 p = accf[j];
        out[(long long)(2 * j)     * Nll + n] = p.x;
        out[(long long)(2 * j + 1) * Nll + n] = p.y;
    }
}

// ---------------------------------------------------------------------------
extern "C" void kernel_launch(void* const* d_in, const int* in_sizes, int n_in,
                              void* d_out, int out_size) {
    const float* A     = (const float*)d_in[0];
    const float* B     = (const float*)d_in[1];
    const float* P     = (const float*)d_in[2];
    const int*   sdims = (const int*)d_in[3];
    const float* svals = (const float*)d_in[4];
    float* out = (float*)d_out;
    int N = in_sizes[0] / ND;
    int ntiles = (N + TB - 1) / TB;

    fused_kernel<<<ntiles + NC, TB>>>(A, B, P, sdims, svals, out, N);
}